// round 14
// baseline (speedup 1.0000x reference)
#include <cuda_runtime.h>
#include <cstdint>

// Problem constants (from reference_code)
#define N_NODES 500000
#define N_EDGES 8000000
#define EBLKS   1184     // 148 SMs x 8 CTAs (256 thr, 32 regs -> full RF, 1 wave)

// ---------------- scratch (device globals: allocation-free) ----------------
// Layer-1 aggregation in 3-dim input space (linearity of x@W1):
//   out1[d] = dinv[d] * (sum_s xs[s] + xs[d]) @ W1 + b1,  xs = x * dinv
__device__ __align__(16) float4 g_xs  [N_NODES];   // (x*dinv, pad) 8 MB, L2-resident
__device__ __align__(16) float4 g_acc [N_NODES];   // layer-1 scatter accumulator, 8 MB
__device__ __align__(8)  float  g_hs2 [N_NODES*2]; // layer-2 scaled features, 4 MB
__device__               float  g_deg [N_NODES];   // degree (incl. self-loop)
__device__               float  g_dinv[N_NODES];   // rsqrt(deg)

#if defined(__CUDA_ARCH__) && __CUDA_ARCH__ >= 900
#define GRID_DEP_SYNC() cudaGridDependencySynchronize()
#else
#define GRID_DEP_SYNC()
#endif

// ---------------- kernels ----------------

__global__ void k_init_deg() {
    int i = blockIdx.x * blockDim.x + threadIdx.x;
    if (i < N_NODES) g_deg[i] = 1.0f;   // self-loop contributes 1
}

// grid-stride persistent: dst histogram (float), 4 edges/iter
__global__ void __launch_bounds__(256) k_degree(const int* __restrict__ ei) {
    GRID_DEP_SYNC();                        // g_deg init visible
    const int4* dp = reinterpret_cast<const int4*>(ei + N_EDGES);
    int stride = gridDim.x * blockDim.x;
    for (int i = blockIdx.x * blockDim.x + threadIdx.x; i < N_EDGES / 4; i += stride) {
        int4 d4 = __ldcs(dp + i);
        atomicAdd(&g_deg[d4.x], 1.0f);
        atomicAdd(&g_deg[d4.y], 1.0f);
        atomicAdd(&g_deg[d4.z], 1.0f);
        atomicAdd(&g_deg[d4.w], 1.0f);
    }
}

// dinv = rsqrt(deg); xs = x * dinv (3-vec in float4); acc = 0
__global__ void k_node1(const float* __restrict__ x) {
    int i = blockIdx.x * blockDim.x + threadIdx.x;
    if (i >= N_NODES) return;
    float x0 = x[3 * i], x1 = x[3 * i + 1], x2 = x[3 * i + 2];  // indep of deg
    GRID_DEP_SYNC();                        // k_degree complete
    float dv = rsqrtf(g_deg[i]);
    g_dinv[i] = dv;
    g_xs [i] = make_float4(x0 * dv, x1 * dv, x2 * dv, 0.f);
    g_acc[i] = make_float4(0.f, 0.f, 0.f, 0.f);
}

#define RED4(ptr, v) \
    asm volatile("red.global.add.v4.f32 [%0], {%1,%2,%3,%4};" \
                 :: "l"(ptr), "f"((v).x), "f"((v).y), "f"((v).z), "f"((v).w) : "memory")
#define RED2(ptr, v) \
    asm volatile("red.global.add.v2.f32 [%0], {%1,%2};" \
                 :: "l"(ptr), "f"((v).x), "f"((v).y) : "memory")

// grid-stride persistent: acc[dst] += xs[src], 4 edges/iter
__global__ void __launch_bounds__(256) k_edge1(const int* __restrict__ ei) {
    GRID_DEP_SYNC();                        // xs/acc ready
    const int4* sp = reinterpret_cast<const int4*>(ei);
    const int4* dp = reinterpret_cast<const int4*>(ei + N_EDGES);
    int stride = gridDim.x * blockDim.x;
    for (int i = blockIdx.x * blockDim.x + threadIdx.x; i < N_EDGES / 4; i += stride) {
        int4 s4 = __ldcs(sp + i);
        int4 d4 = __ldcs(dp + i);
        float4 v0 = __ldcg(&g_xs[s4.x]);
        float4 v1 = __ldcg(&g_xs[s4.y]);
        float4 v2 = __ldcg(&g_xs[s4.z]);
        float4 v3 = __ldcg(&g_xs[s4.w]);
        RED4(&g_acc[d4.x], v0);
        RED4(&g_acc[d4.y], v1);
        RED4(&g_acc[d4.z], v2);
        RED4(&g_acc[d4.w], v3);
    }
}

// t = dinv*(acc + xs); a = relu(t@W1 + b1); hs2 = (a@W2)*dinv;
// out initialized with the self-loop term hs2[d]
__global__ void k_node2(const float* __restrict__ W1, const float* __restrict__ b1,
                        const float* __restrict__ W2, float* __restrict__ out) {
    int i = blockIdx.x * blockDim.x + threadIdx.x;
    if (i >= N_NODES) return;
    GRID_DEP_SYNC();                        // acc complete
    float dv = g_dinv[i];
    float4 xs = g_xs[i];
    float4 ac = g_acc[i];
    float t0 = dv * (ac.x + xs.x);
    float t1 = dv * (ac.y + xs.y);
    float t2 = dv * (ac.z + xs.z);
    float a[8];
#pragma unroll
    for (int j = 0; j < 8; j++) {
        float v = t0 * __ldg(&W1[j]) + t1 * __ldg(&W1[8 + j]) + t2 * __ldg(&W1[16 + j])
                  + __ldg(&b1[j]);
        a[j] = fmaxf(v, 0.0f);
    }
    float o0 = 0.f, o1 = 0.f;
#pragma unroll
    for (int j = 0; j < 8; j++) {
        o0 += a[j] * __ldg(&W2[2 * j]);
        o1 += a[j] * __ldg(&W2[2 * j + 1]);
    }
    float2 h = make_float2(o0 * dv, o1 * dv);
    reinterpret_cast<float2*>(&g_hs2[(size_t)i * 2])[0] = h;
    reinterpret_cast<float2*>(&out[(size_t)i * 2])[0]   = h;   // self-loop term
}

// grid-stride persistent: out[dst] += hs2[src], 4 edges/iter
__global__ void __launch_bounds__(256) k_edge2(const int* __restrict__ ei,
                                               float* __restrict__ out) {
    GRID_DEP_SYNC();                        // hs2 + self-term ready
    const int4* sp = reinterpret_cast<const int4*>(ei);
    const int4* dp = reinterpret_cast<const int4*>(ei + N_EDGES);
    const float2* hs = reinterpret_cast<const float2*>(g_hs2);
    int stride = gridDim.x * blockDim.x;
    for (int i = blockIdx.x * blockDim.x + threadIdx.x; i < N_EDGES / 4; i += stride) {
        int4 s4 = __ldcs(sp + i);
        int4 d4 = __ldcs(dp + i);
        float2 v0 = __ldcg(hs + s4.x);
        float2 v1 = __ldcg(hs + s4.y);
        float2 v2 = __ldcg(hs + s4.z);
        float2 v3 = __ldcg(hs + s4.w);
        RED2(out + (size_t)d4.x * 2, v0);
        RED2(out + (size_t)d4.y * 2, v1);
        RED2(out + (size_t)d4.z * 2, v2);
        RED2(out + (size_t)d4.w * 2, v3);
    }
}

// out = dinv*out + b2   (self term already included at init)
__global__ void k_fin(const float* __restrict__ b2, float* __restrict__ out) {
    int i = blockIdx.x * blockDim.x + threadIdx.x;
    if (i >= N_NODES) return;
    GRID_DEP_SYNC();                        // all edge2 REDs complete
    float dv = g_dinv[i];
    float2* op = reinterpret_cast<float2*>(&out[(size_t)i * 2]);
    float2 acc = op[0];
    op[0] = make_float2(dv * acc.x + __ldg(&b2[0]),
                        dv * acc.y + __ldg(&b2[1]));
}

// ---------------- PDL launch helper ----------------
template <typename K, typename... Args>
static inline void launch_pdl(K kernel, int grid, int block, Args... args) {
    cudaLaunchConfig_t cfg = {};
    cfg.gridDim = dim3(grid, 1, 1);
    cfg.blockDim = dim3(block, 1, 1);
    cfg.dynamicSmemBytes = 0;
    cfg.stream = 0;
    cudaLaunchAttribute attr[1];
    attr[0].id = cudaLaunchAttributeProgrammaticStreamSerialization;
    attr[0].val.programmaticStreamSerializationAllowed = 1;
    cfg.attrs = attr;
    cfg.numAttrs = 1;
    cudaLaunchKernelEx(&cfg, kernel, args...);
}

// ---------------- launch ----------------
extern "C" void kernel_launch(void* const* d_in, const int* in_sizes, int n_in,
                              void* d_out, int out_size) {
    const float* x  = (const float*)d_in[0];   // [N, 3] f32
    const int*   ei = (const int*)d_in[1];     // [2, E] int32
    const float* W1 = (const float*)d_in[2];   // [3, 8]
    const float* b1 = (const float*)d_in[3];   // [8]
    const float* W2 = (const float*)d_in[4];   // [8, 2]
    const float* b2 = (const float*)d_in[5];   // [2]
    float* out = (float*)d_out;                // [N, 2] f32

    const int TB = 256;
    const int gN = (N_NODES + TB - 1) / TB;

    launch_pdl(k_init_deg, gN,    TB);
    launch_pdl(k_degree,   EBLKS, TB, ei);
    launch_pdl(k_node1,    gN,    TB, x);
    launch_pdl(k_edge1,    EBLKS, TB, ei);
    launch_pdl(k_node2,    gN,    TB, W1, b1, W2, out);
    launch_pdl(k_edge2,    EBLKS, TB, ei, out);
    launch_pdl(k_fin,      gN,    TB, b2, out);
}

// round 15
// speedup vs baseline: 1.0263x; 1.0263x over previous
#include <cuda_runtime.h>
#include <cstdint>

// Problem constants (from reference_code)
#define N_NODES 500000
#define N_EDGES 8000000

// ---------------- scratch (device globals: allocation-free) ----------------
// Layer-1 aggregation in 3-dim input space (linearity of x@W1):
//   out1[d] = dinv[d] * (sum_s xs[s] + xs[d]) @ W1 + b1,  xs = x * dinv
__device__ __align__(16) float4 g_xs  [N_NODES];   // (x*dinv, pad) 8 MB, L2-resident
__device__ __align__(16) float4 g_acc [N_NODES];   // layer-1 scatter accumulator, 8 MB
__device__ __align__(8)  float  g_hs2 [N_NODES*2]; // layer-2 scaled features, 4 MB
__device__ __align__(16) float  g_deg [N_NODES];   // degree (incl. self-loop)
__device__ __align__(16) float  g_dinv[N_NODES];   // rsqrt(deg)

#if defined(__CUDA_ARCH__) && __CUDA_ARCH__ >= 900
#define GRID_DEP_SYNC() cudaGridDependencySynchronize()
#else
#define GRID_DEP_SYNC()
#endif

// ---------------- kernels ----------------

__global__ void k_init_deg() {
    int i = blockIdx.x * blockDim.x + threadIdx.x;
    if (i < N_NODES) g_deg[i] = 1.0f;   // self-loop contributes 1
}

// 4 edges/thread; index loads issued BEFORE the PDL sync (prefetch during
// predecessor drain — measured win in R13)
__global__ void __launch_bounds__(256) k_degree(const int* __restrict__ ei) {
    int i = blockIdx.x * blockDim.x + threadIdx.x;
    if (i >= N_EDGES / 4) return;
    int4 d4 = __ldcs(reinterpret_cast<const int4*>(ei + N_EDGES) + i);
    GRID_DEP_SYNC();                    // g_deg init visible before atomics
    atomicAdd(&g_deg[d4.x], 1.0f);
    atomicAdd(&g_deg[d4.y], 1.0f);
    atomicAdd(&g_deg[d4.z], 1.0f);
    atomicAdd(&g_deg[d4.w], 1.0f);
}

// 4 nodes/thread, fully vectorized: 3x float4 x-loads, float4 deg/dinv,
// float4 xs/acc stores.  500000 % 4 == 0.
__global__ void k_node1(const float* __restrict__ x) {
    int t = blockIdx.x * blockDim.x + threadIdx.x;
    if (t >= N_NODES / 4) return;
    int n = t * 4;
    const float4* xp = reinterpret_cast<const float4*>(x) + t * 3;
    float4 a = __ldcs(xp);
    float4 b = __ldcs(xp + 1);
    float4 c = __ldcs(xp + 2);
    GRID_DEP_SYNC();                    // k_degree complete before reading g_deg
    float4 dg = *reinterpret_cast<const float4*>(&g_deg[n]);
    float4 dv = make_float4(rsqrtf(dg.x), rsqrtf(dg.y), rsqrtf(dg.z), rsqrtf(dg.w));
    *reinterpret_cast<float4*>(&g_dinv[n]) = dv;
    g_xs[n + 0] = make_float4(a.x * dv.x, a.y * dv.x, a.z * dv.x, 0.f);
    g_xs[n + 1] = make_float4(a.w * dv.y, b.x * dv.y, b.y * dv.y, 0.f);
    g_xs[n + 2] = make_float4(b.z * dv.z, b.w * dv.z, c.x * dv.z, 0.f);
    g_xs[n + 3] = make_float4(c.y * dv.w, c.z * dv.w, c.w * dv.w, 0.f);
    float4 z = make_float4(0.f, 0.f, 0.f, 0.f);
    g_acc[n + 0] = z;
    g_acc[n + 1] = z;
    g_acc[n + 2] = z;
    g_acc[n + 3] = z;
}

#define RED4(ptr, v) \
    asm volatile("red.global.add.v4.f32 [%0], {%1,%2,%3,%4};" \
                 :: "l"(ptr), "f"((v).x), "f"((v).y), "f"((v).z), "f"((v).w) : "memory")
#define RED2(ptr, v) \
    asm volatile("red.global.add.v2.f32 [%0], {%1,%2};" \
                 :: "l"(ptr), "f"((v).x), "f"((v).y) : "memory")

// acc[dst] += xs[src]; 4 edges/thread (measured optimum)
__global__ void __launch_bounds__(256) k_edge1(const int* __restrict__ ei) {
    int i = blockIdx.x * blockDim.x + threadIdx.x;
    if (i >= N_EDGES / 4) return;
    int4 s4 = __ldcs(reinterpret_cast<const int4*>(ei) + i);
    int4 d4 = __ldcs(reinterpret_cast<const int4*>(ei + N_EDGES) + i);
    GRID_DEP_SYNC();                    // xs/acc ready
    float4 v0 = __ldcg(&g_xs[s4.x]);
    float4 v1 = __ldcg(&g_xs[s4.y]);
    float4 v2 = __ldcg(&g_xs[s4.z]);
    float4 v3 = __ldcg(&g_xs[s4.w]);
    RED4(&g_acc[d4.x], v0);
    RED4(&g_acc[d4.y], v1);
    RED4(&g_acc[d4.z], v2);
    RED4(&g_acc[d4.w], v3);
}

// t = dinv*(acc + xs); a = relu(t@W1 + b1); hs2 = (a@W2)*dinv;
// out initialized with the self-loop term hs2[d] (k_fin then just scales+biases)
__global__ void k_node2(const float* __restrict__ W1, const float* __restrict__ b1,
                        const float* __restrict__ W2, float* __restrict__ out) {
    int i = blockIdx.x * blockDim.x + threadIdx.x;
    if (i >= N_NODES) return;
    GRID_DEP_SYNC();                    // acc complete
    float dv = g_dinv[i];
    float4 xs = g_xs[i];
    float4 ac = g_acc[i];
    float t0 = dv * (ac.x + xs.x);
    float t1 = dv * (ac.y + xs.y);
    float t2 = dv * (ac.z + xs.z);
    float a[8];
#pragma unroll
    for (int j = 0; j < 8; j++) {
        float v = t0 * __ldg(&W1[j]) + t1 * __ldg(&W1[8 + j]) + t2 * __ldg(&W1[16 + j])
                  + __ldg(&b1[j]);
        a[j] = fmaxf(v, 0.0f);
    }
    float o0 = 0.f, o1 = 0.f;
#pragma unroll
    for (int j = 0; j < 8; j++) {
        o0 += a[j] * __ldg(&W2[2 * j]);
        o1 += a[j] * __ldg(&W2[2 * j + 1]);
    }
    float2 h = make_float2(o0 * dv, o1 * dv);
    reinterpret_cast<float2*>(&g_hs2[(size_t)i * 2])[0] = h;
    reinterpret_cast<float2*>(&out[(size_t)i * 2])[0]   = h;   // self-loop term
}

// out[dst] += hs2[src]; 4 edges/thread
__global__ void __launch_bounds__(256) k_edge2(const int* __restrict__ ei,
                                               float* __restrict__ out) {
    int i = blockIdx.x * blockDim.x + threadIdx.x;
    if (i >= N_EDGES / 4) return;
    int4 s4 = __ldcs(reinterpret_cast<const int4*>(ei) + i);
    int4 d4 = __ldcs(reinterpret_cast<const int4*>(ei + N_EDGES) + i);
    GRID_DEP_SYNC();                    // hs2 + out self-term ready
    const float2* hs = reinterpret_cast<const float2*>(g_hs2);
    float2 v0 = __ldcg(hs + s4.x);
    float2 v1 = __ldcg(hs + s4.y);
    float2 v2 = __ldcg(hs + s4.z);
    float2 v3 = __ldcg(hs + s4.w);
    RED2(out + (size_t)d4.x * 2, v0);
    RED2(out + (size_t)d4.y * 2, v1);
    RED2(out + (size_t)d4.z * 2, v2);
    RED2(out + (size_t)d4.w * 2, v3);
}

// out = dinv*out + b2   (self term already included at init)
__global__ void k_fin(const float* __restrict__ b2, float* __restrict__ out) {
    int i = blockIdx.x * blockDim.x + threadIdx.x;
    if (i >= N_NODES) return;
    GRID_DEP_SYNC();                    // all edge2 REDs complete
    float dv = g_dinv[i];
    float2* op = reinterpret_cast<float2*>(&out[(size_t)i * 2]);
    float2 acc = op[0];
    op[0] = make_float2(dv * acc.x + __ldg(&b2[0]),
                        dv * acc.y + __ldg(&b2[1]));
}

// ---------------- PDL launch helper ----------------
template <typename K, typename... Args>
static inline void launch_pdl(K kernel, int grid, int block, Args... args) {
    cudaLaunchConfig_t cfg = {};
    cfg.gridDim = dim3(grid, 1, 1);
    cfg.blockDim = dim3(block, 1, 1);
    cfg.dynamicSmemBytes = 0;
    cfg.stream = 0;
    cudaLaunchAttribute attr[1];
    attr[0].id = cudaLaunchAttributeProgrammaticStreamSerialization;
    attr[0].val.programmaticStreamSerializationAllowed = 1;
    cfg.attrs = attr;
    cfg.numAttrs = 1;
    cudaLaunchKernelEx(&cfg, kernel, args...);
}

// ---------------- launch ----------------
extern "C" void kernel_launch(void* const* d_in, const int* in_sizes, int n_in,
                              void* d_out, int out_size) {
    const float* x  = (const float*)d_in[0];   // [N, 3] f32
    const int*   ei = (const int*)d_in[1];     // [2, E] int32
    const float* W1 = (const float*)d_in[2];   // [3, 8]
    const float* b1 = (const float*)d_in[3];   // [8]
    const float* W2 = (const float*)d_in[4];   // [8, 2]
    const float* b2 = (const float*)d_in[5];   // [2]
    float* out = (float*)d_out;                // [N, 2] f32

    const int TB  = 256;
    const int gN  = (N_NODES + TB - 1) / TB;
    const int gN4 = (N_NODES / 4 + TB - 1) / TB;
    const int gE4 = (N_EDGES / 4 + TB - 1) / TB;

    launch_pdl(k_init_deg, gN,  TB);
    launch_pdl(k_degree,   gE4, TB, ei);
    launch_pdl(k_node1,    gN4, TB, x);
    launch_pdl(k_edge1,    gE4, TB, ei);
    launch_pdl(k_node2,    gN,  TB, W1, b1, W2, out);
    launch_pdl(k_edge2,    gE4, TB, ei, out);
    launch_pdl(k_fin,      gN,  TB, b2, out);
}

// round 16
// speedup vs baseline: 1.0490x; 1.0221x over previous
#include <cuda_runtime.h>
#include <cstdint>

// Problem constants (from reference_code)
#define N_NODES 500000
#define N_EDGES 8000000

// ---------------- scratch (device globals: allocation-free) ----------------
// Layer-1 aggregation in 3-dim input space (linearity of x@W1):
//   out1[d] = dinv[d] * (sum_s xs[s] + xs[d]) @ W1 + b1,  xs = x * dinv
__device__ __align__(16) float4 g_xs  [N_NODES];   // (x*dinv, pad) 8 MB, L2-resident
__device__ __align__(16) float4 g_acc [N_NODES];   // layer-1 scatter accumulator, 8 MB
__device__ __align__(8)  float  g_hs2 [N_NODES*2]; // layer-2 scaled features, 4 MB
__device__               float  g_deg [N_NODES];   // degree (incl. self-loop)
__device__               float  g_dinv[N_NODES];   // rsqrt(deg)

#if defined(__CUDA_ARCH__) && __CUDA_ARCH__ >= 900
#define GRID_DEP_SYNC() cudaGridDependencySynchronize()
#else
#define GRID_DEP_SYNC()
#endif

// ---------------- kernels ----------------

__global__ void k_init_deg() {
    // no predecessor data dependency (first kernel)
    int i = blockIdx.x * blockDim.x + threadIdx.x;
    if (i < N_NODES) g_deg[i] = 1.0f;   // self-loop contributes 1
}

// 4 edges per thread; index loads issued BEFORE the PDL sync so the 64MB
// stream prefetches while the predecessor kernel drains (measured win, R13)
__global__ void __launch_bounds__(256) k_degree(const int* __restrict__ ei) {
    int i = blockIdx.x * blockDim.x + threadIdx.x;
    if (i >= N_EDGES / 4) return;
    int4 d4 = __ldcs(reinterpret_cast<const int4*>(ei + N_EDGES) + i);
    GRID_DEP_SYNC();                    // g_deg init must be visible before atomics
    atomicAdd(&g_deg[d4.x], 1.0f);
    atomicAdd(&g_deg[d4.y], 1.0f);
    atomicAdd(&g_deg[d4.z], 1.0f);
    atomicAdd(&g_deg[d4.w], 1.0f);
}

// dinv = rsqrt(deg); xs = x * dinv (3-vec in float4); acc = 0
__global__ void k_node1(const float* __restrict__ x) {
    int i = blockIdx.x * blockDim.x + threadIdx.x;
    if (i >= N_NODES) return;
    float x0 = x[3 * i], x1 = x[3 * i + 1], x2 = x[3 * i + 2];  // independent of deg
    GRID_DEP_SYNC();                    // wait for k_degree before reading g_deg
    float dv = rsqrtf(g_deg[i]);
    g_dinv[i] = dv;
    g_xs [i] = make_float4(x0 * dv, x1 * dv, x2 * dv, 0.f);
    g_acc[i] = make_float4(0.f, 0.f, 0.f, 0.f);
}

#define RED4(ptr, v) \
    asm volatile("red.global.add.v4.f32 [%0], {%1,%2,%3,%4};" \
                 :: "l"(ptr), "f"((v).x), "f"((v).y), "f"((v).z), "f"((v).w) : "memory")
#define RED2(ptr, v) \
    asm volatile("red.global.add.v2.f32 [%0], {%1,%2};" \
                 :: "l"(ptr), "f"((v).x), "f"((v).y) : "memory")

// acc[dst] += xs[src]; 4 edges/thread (measured optimum)
__global__ void __launch_bounds__(256) k_edge1(const int* __restrict__ ei) {
    int i = blockIdx.x * blockDim.x + threadIdx.x;
    if (i >= N_EDGES / 4) return;
    int4 s4 = __ldcs(reinterpret_cast<const int4*>(ei) + i);
    int4 d4 = __ldcs(reinterpret_cast<const int4*>(ei + N_EDGES) + i);
    GRID_DEP_SYNC();                    // xs/acc ready
    float4 v0 = __ldcg(&g_xs[s4.x]);
    float4 v1 = __ldcg(&g_xs[s4.y]);
    float4 v2 = __ldcg(&g_xs[s4.z]);
    float4 v3 = __ldcg(&g_xs[s4.w]);
    RED4(&g_acc[d4.x], v0);
    RED4(&g_acc[d4.y], v1);
    RED4(&g_acc[d4.z], v2);
    RED4(&g_acc[d4.w], v3);
}

// t = dinv*(acc + xs); a = relu(t@W1 + b1); hs2 = (a@W2)*dinv;
// out initialized with the self-loop term hs2[d] (k_fin then just scales+biases)
__global__ void k_node2(const float* __restrict__ W1, const float* __restrict__ b1,
                        const float* __restrict__ W2, float* __restrict__ out) {
    int i = blockIdx.x * blockDim.x + threadIdx.x;
    if (i >= N_NODES) return;
    GRID_DEP_SYNC();                    // acc complete
    float dv = g_dinv[i];
    float4 xs = g_xs[i];
    float4 ac = g_acc[i];
    float t0 = dv * (ac.x + xs.x);
    float t1 = dv * (ac.y + xs.y);
    float t2 = dv * (ac.z + xs.z);
    float a[8];
#pragma unroll
    for (int j = 0; j < 8; j++) {
        float v = t0 * __ldg(&W1[j]) + t1 * __ldg(&W1[8 + j]) + t2 * __ldg(&W1[16 + j])
                  + __ldg(&b1[j]);
        a[j] = fmaxf(v, 0.0f);
    }
    float o0 = 0.f, o1 = 0.f;
#pragma unroll
    for (int j = 0; j < 8; j++) {
        o0 += a[j] * __ldg(&W2[2 * j]);
        o1 += a[j] * __ldg(&W2[2 * j + 1]);
    }
    float2 h = make_float2(o0 * dv, o1 * dv);
    reinterpret_cast<float2*>(&g_hs2[(size_t)i * 2])[0] = h;
    reinterpret_cast<float2*>(&out[(size_t)i * 2])[0]   = h;   // self-loop term
}

// out[dst] += hs2[src]; 4 edges/thread
__global__ void __launch_bounds__(256) k_edge2(const int* __restrict__ ei,
                                               float* __restrict__ out) {
    int i = blockIdx.x * blockDim.x + threadIdx.x;
    if (i >= N_EDGES / 4) return;
    int4 s4 = __ldcs(reinterpret_cast<const int4*>(ei) + i);
    int4 d4 = __ldcs(reinterpret_cast<const int4*>(ei + N_EDGES) + i);
    GRID_DEP_SYNC();                    // hs2 + out self-term ready
    const float2* hs = reinterpret_cast<const float2*>(g_hs2);
    float2 v0 = __ldcg(hs + s4.x);
    float2 v1 = __ldcg(hs + s4.y);
    float2 v2 = __ldcg(hs + s4.z);
    float2 v3 = __ldcg(hs + s4.w);
    RED2(out + (size_t)d4.x * 2, v0);
    RED2(out + (size_t)d4.y * 2, v1);
    RED2(out + (size_t)d4.z * 2, v2);
    RED2(out + (size_t)d4.w * 2, v3);
}

// out = dinv*out + b2   (self term already included at init)
__global__ void k_fin(const float* __restrict__ b2, float* __restrict__ out) {
    int i = blockIdx.x * blockDim.x + threadIdx.x;
    if (i >= N_NODES) return;
    GRID_DEP_SYNC();                    // all edge2 REDs complete
    float dv = g_dinv[i];
    float2* op = reinterpret_cast<float2*>(&out[(size_t)i * 2]);
    float2 acc = op[0];
    op[0] = make_float2(dv * acc.x + __ldg(&b2[0]),
                        dv * acc.y + __ldg(&b2[1]));
}

// ---------------- PDL launch helper ----------------
template <typename K, typename... Args>
static inline void launch_pdl(K kernel, int grid, int block, Args... args) {
    cudaLaunchConfig_t cfg = {};
    cfg.gridDim = dim3(grid, 1, 1);
    cfg.blockDim = dim3(block, 1, 1);
    cfg.dynamicSmemBytes = 0;
    cfg.stream = 0;                         // legacy default stream (capture-visible)
    cudaLaunchAttribute attr[1];
    attr[0].id = cudaLaunchAttributeProgrammaticStreamSerialization;
    attr[0].val.programmaticStreamSerializationAllowed = 1;
    cfg.attrs = attr;
    cfg.numAttrs = 1;
    cudaLaunchKernelEx(&cfg, kernel, args...);
}

// ---------------- launch ----------------
extern "C" void kernel_launch(void* const* d_in, const int* in_sizes, int n_in,
                              void* d_out, int out_size) {
    const float* x  = (const float*)d_in[0];   // [N, 3] f32
    const int*   ei = (const int*)d_in[1];     // [2, E] int32
    const float* W1 = (const float*)d_in[2];   // [3, 8]
    const float* b1 = (const float*)d_in[3];   // [8]
    const float* W2 = (const float*)d_in[4];   // [8, 2]
    const float* b2 = (const float*)d_in[5];   // [2]
    float* out = (float*)d_out;                // [N, 2] f32

    const int TB = 256;
    const int gN  = (N_NODES + TB - 1) / TB;
    const int gE4 = (N_EDGES / 4 + TB - 1) / TB;

    launch_pdl(k_init_deg, gN,  TB);
    launch_pdl(k_degree,   gE4, TB, ei);
    launch_pdl(k_node1,    gN,  TB, x);
    launch_pdl(k_edge1,    gE4, TB, ei);
    launch_pdl(k_node2,    gN,  TB, W1, b1, W2, out);
    launch_pdl(k_edge2,    gE4, TB, ei, out);
    launch_pdl(k_fin,      gN,  TB, b2, out);
}

// round 17
// speedup vs baseline: 1.0838x; 1.0332x over previous
#include <cuda_runtime.h>
#include <cstdint>

// Problem constants (from reference_code)
#define N_NODES 500000
#define N_EDGES 8000000

// ---------------- scratch (device globals: allocation-free) ----------------
// Layer-1 aggregation in 3-dim input space (linearity of x@W1):
//   out1[d] = dinv[d] * (xs[d] + sum_s xs[s]) @ W1 + b1,  xs = x * dinv
// g_acc is initialized to xs (self-loop term folded at init).
__device__ __align__(16) float4 g_xs  [N_NODES];   // (x*dinv, pad) 8 MB, L2-resident
__device__ __align__(16) float4 g_acc [N_NODES];   // self + scatter accumulator, 8 MB
__device__ __align__(8)  float  g_hs2 [N_NODES*2]; // layer-2 scaled features, 4 MB
__device__               float  g_deg [N_NODES];   // degree (incl. self-loop)
__device__               float  g_dinv[N_NODES];   // rsqrt(deg)

#if defined(__CUDA_ARCH__) && __CUDA_ARCH__ >= 900
#define GRID_DEP_SYNC() cudaGridDependencySynchronize()
#else
#define GRID_DEP_SYNC()
#endif

// ---------------- kernels ----------------

__global__ void k_init_deg() {
    int i = blockIdx.x * blockDim.x + threadIdx.x;
    if (i < N_NODES) g_deg[i] = 1.0f;   // self-loop contributes 1
}

// 4 edges per thread; index loads issued BEFORE the PDL sync so the 64MB
// stream prefetches while the predecessor kernel drains (measured win, R13)
__global__ void __launch_bounds__(256) k_degree(const int* __restrict__ ei) {
    int i = blockIdx.x * blockDim.x + threadIdx.x;
    if (i >= N_EDGES / 4) return;
    int4 d4 = __ldcs(reinterpret_cast<const int4*>(ei + N_EDGES) + i);
    GRID_DEP_SYNC();                    // g_deg init must be visible before atomics
    atomicAdd(&g_deg[d4.x], 1.0f);
    atomicAdd(&g_deg[d4.y], 1.0f);
    atomicAdd(&g_deg[d4.z], 1.0f);
    atomicAdd(&g_deg[d4.w], 1.0f);
}

// dinv = rsqrt(deg); xs = x * dinv; acc initialized to xs (self term)
__global__ void k_node1(const float* __restrict__ x) {
    int i = blockIdx.x * blockDim.x + threadIdx.x;
    if (i >= N_NODES) return;
    float x0 = x[3 * i], x1 = x[3 * i + 1], x2 = x[3 * i + 2];  // independent of deg
    GRID_DEP_SYNC();                    // wait for k_degree before reading g_deg
    float dv = rsqrtf(g_deg[i]);
    g_dinv[i] = dv;
    float4 v = make_float4(x0 * dv, x1 * dv, x2 * dv, 0.f);
    g_xs [i] = v;
    g_acc[i] = v;                       // self-loop term pre-folded
}

#define RED4(ptr, v) \
    asm volatile("red.global.add.v4.f32 [%0], {%1,%2,%3,%4};" \
                 :: "l"(ptr), "f"((v).x), "f"((v).y), "f"((v).z), "f"((v).w) : "memory")
#define RED2(ptr, v) \
    asm volatile("red.global.add.v2.f32 [%0], {%1,%2};" \
                 :: "l"(ptr), "f"((v).x), "f"((v).y) : "memory")

// acc[dst] += xs[src]; 4 edges/thread (measured optimum)
__global__ void __launch_bounds__(256) k_edge1(const int* __restrict__ ei) {
    int i = blockIdx.x * blockDim.x + threadIdx.x;
    if (i >= N_EDGES / 4) return;
    int4 s4 = __ldcs(reinterpret_cast<const int4*>(ei) + i);
    int4 d4 = __ldcs(reinterpret_cast<const int4*>(ei + N_EDGES) + i);
    GRID_DEP_SYNC();                    // xs/acc ready
    float4 v0 = __ldcg(&g_xs[s4.x]);
    float4 v1 = __ldcg(&g_xs[s4.y]);
    float4 v2 = __ldcg(&g_xs[s4.z]);
    float4 v3 = __ldcg(&g_xs[s4.w]);
    RED4(&g_acc[d4.x], v0);
    RED4(&g_acc[d4.y], v1);
    RED4(&g_acc[d4.z], v2);
    RED4(&g_acc[d4.w], v3);
}

// t = dinv*acc (self term already in acc); a = relu(t@W1 + b1);
// hs2 = (a@W2)*dinv; out initialized with the self-loop term hs2[d]
__global__ void k_node2(const float* __restrict__ W1, const float* __restrict__ b1,
                        const float* __restrict__ W2, float* __restrict__ out) {
    int i = blockIdx.x * blockDim.x + threadIdx.x;
    if (i >= N_NODES) return;
    GRID_DEP_SYNC();                    // acc complete
    float dv = g_dinv[i];
    float4 ac = g_acc[i];
    float t0 = dv * ac.x;
    float t1 = dv * ac.y;
    float t2 = dv * ac.z;
    float a[8];
#pragma unroll
    for (int j = 0; j < 8; j++) {
        float v = t0 * __ldg(&W1[j]) + t1 * __ldg(&W1[8 + j]) + t2 * __ldg(&W1[16 + j])
                  + __ldg(&b1[j]);
        a[j] = fmaxf(v, 0.0f);
    }
    float o0 = 0.f, o1 = 0.f;
#pragma unroll
    for (int j = 0; j < 8; j++) {
        o0 += a[j] * __ldg(&W2[2 * j]);
        o1 += a[j] * __ldg(&W2[2 * j + 1]);
    }
    float2 h = make_float2(o0 * dv, o1 * dv);
    reinterpret_cast<float2*>(&g_hs2[(size_t)i * 2])[0] = h;
    reinterpret_cast<float2*>(&out[(size_t)i * 2])[0]   = h;   // self-loop term
}

// out[dst] += hs2[src]; 4 edges/thread
__global__ void __launch_bounds__(256) k_edge2(const int* __restrict__ ei,
                                               float* __restrict__ out) {
    int i = blockIdx.x * blockDim.x + threadIdx.x;
    if (i >= N_EDGES / 4) return;
    int4 s4 = __ldcs(reinterpret_cast<const int4*>(ei) + i);
    int4 d4 = __ldcs(reinterpret_cast<const int4*>(ei + N_EDGES) + i);
    GRID_DEP_SYNC();                    // hs2 + out self-term ready
    const float2* hs = reinterpret_cast<const float2*>(g_hs2);
    float2 v0 = __ldcg(hs + s4.x);
    float2 v1 = __ldcg(hs + s4.y);
    float2 v2 = __ldcg(hs + s4.z);
    float2 v3 = __ldcg(hs + s4.w);
    RED2(out + (size_t)d4.x * 2, v0);
    RED2(out + (size_t)d4.y * 2, v1);
    RED2(out + (size_t)d4.z * 2, v2);
    RED2(out + (size_t)d4.w * 2, v3);
}

// out = dinv*out + b2   (self term already included at init)
__global__ void k_fin(const float* __restrict__ b2, float* __restrict__ out) {
    int i = blockIdx.x * blockDim.x + threadIdx.x;
    if (i >= N_NODES) return;
    GRID_DEP_SYNC();                    // all edge2 REDs complete
    float dv = g_dinv[i];
    float2* op = reinterpret_cast<float2*>(&out[(size_t)i * 2]);
    float2 acc = op[0];
    op[0] = make_float2(dv * acc.x + __ldg(&b2[0]),
                        dv * acc.y + __ldg(&b2[1]));
}

// ---------------- PDL launch helper ----------------
template <typename K, typename... Args>
static inline void launch_pdl(K kernel, int grid, int block, Args... args) {
    cudaLaunchConfig_t cfg = {};
    cfg.gridDim = dim3(grid, 1, 1);
    cfg.blockDim = dim3(block, 1, 1);
    cfg.dynamicSmemBytes = 0;
    cfg.stream = 0;                         // legacy default stream (capture-visible)
    cudaLaunchAttribute attr[1];
    attr[0].id = cudaLaunchAttributeProgrammaticStreamSerialization;
    attr[0].val.programmaticStreamSerializationAllowed = 1;
    cfg.attrs = attr;
    cfg.numAttrs = 1;
    cudaLaunchKernelEx(&cfg, kernel, args...);
}

// ---------------- launch ----------------
extern "C" void kernel_launch(void* const* d_in, const int* in_sizes, int n_in,
                              void* d_out, int out_size) {
    const float* x  = (const float*)d_in[0];   // [N, 3] f32
    const int*   ei = (const int*)d_in[1];     // [2, E] int32
    const float* W1 = (const float*)d_in[2];   // [3, 8]
    const float* b1 = (const float*)d_in[3];   // [8]
    const float* W2 = (const float*)d_in[4];   // [8, 2]
    const float* b2 = (const float*)d_in[5];   // [2]
    float* out = (float*)d_out;                // [N, 2] f32

    const int TB = 256;
    const int gN  = (N_NODES + TB - 1) / TB;
    const int gE4 = (N_EDGES / 4 + TB - 1) / TB;

    launch_pdl(k_init_deg, gN,  TB);
    launch_pdl(k_degree,   gE4, TB, ei);
    launch_pdl(k_node1,    gN,  TB, x);
    launch_pdl(k_edge1,    gE4, TB, ei);
    launch_pdl(k_node2,    gN,  TB, W1, b1, W2, out);
    launch_pdl(k_edge2,    gE4, TB, ei, out);
    launch_pdl(k_fin,      gN,  TB, b2, out);
}